// round 11
// baseline (speedup 1.0000x reference)
#include <cuda_runtime.h>
#include <cuda_fp16.h>
#include <cstdint>
#include <math.h>

#define HD 512
#define BB 128
#define SSQ 2048
#define MT 128        // s-rows per block
#define NT 256        // n-cols per block (half of HD)
#define KC 32
#define NCH (HD / KC) // 16
#define ROWB 80       // padded smem row bytes (40 fp16, 64 valid) — conflict-free
#define GT 256        // gemm threads (8 warps, 2x4 grid of 64x64 tiles)

// stage: A[128][80] @0 (10240), B[256][80] @10240 (20480) => 30720/stage, 2 stages
#define OF_Bb 10240
#define STGSZ 30720
#define OF_PART (2 * STGSZ)           // 61440, float[4][128] = 2KB
#define OF_CV (OF_PART + 2048)        // 63488, float2[256] = 2KB
#define SMEM_TOTAL (OF_CV + 2048)     // 65536

// ---------------- device scratch ----------------
__device__ float g_c[BB * HD];
__device__ float g_scores[BB * SSQ];
__device__ float g_part[2][BB * SSQ];
__device__ float g_cpart[4][BB * HD];
__device__ __align__(16) __half g_K16[(size_t)BB * SSQ * HD];  // fp16 keys (by GEMM nh=0)
__device__ __align__(16) __half g_UaP[(size_t)NCH * HD * 40];  // [kc][n][40] halves, 80B/row

// ---------------- helpers ----------------
__device__ __forceinline__ uint32_t smem_u32(const void* p) {
    uint32_t a;
    asm("{ .reg .u64 t; cvta.to.shared.u64 t, %1; cvt.u32.u64 %0, t; }" : "=r"(a) : "l"(p));
    return a;
}
__device__ __forceinline__ void cpasync16(uint32_t dst, const void* src) {
    asm volatile("cp.async.cg.shared.global [%0], [%1], 16;" :: "r"(dst), "l"(src));
}
__device__ __forceinline__ void cpasync_commit() {
    asm volatile("cp.async.commit_group;" ::: "memory");
}
__device__ __forceinline__ void cpasync_waitall() {
    asm volatile("cp.async.wait_group 0;" ::: "memory");
}
__device__ __forceinline__ void ldsm4(uint32_t (&r)[4], uint32_t addr) {
    asm volatile("ldmatrix.sync.aligned.m8n8.x4.shared.b16 {%0,%1,%2,%3}, [%4];"
                 : "=r"(r[0]), "=r"(r[1]), "=r"(r[2]), "=r"(r[3]) : "r"(addr));
}
__device__ __forceinline__ void mma16816(float (&d)[4], const uint32_t (&a)[4],
                                         uint32_t b0, uint32_t b1) {
    asm volatile(
        "mma.sync.aligned.m16n8k16.row.col.f32.f16.f16.f32 "
        "{%0,%1,%2,%3}, {%4,%5,%6,%7}, {%8,%9}, {%0,%1,%2,%3};"
        : "+f"(d[0]), "+f"(d[1]), "+f"(d[2]), "+f"(d[3])
        : "r"(a[0]), "r"(a[1]), "r"(a[2]), "r"(a[3]), "r"(b0), "r"(b1));
}

// ---------------- fused prep: Ua pack | c = q@Wa^T + ba + bu ----------------
__global__ void __launch_bounds__(512)
prep_kernel(const float* __restrict__ Ua, const float* __restrict__ Wa,
            const float* __restrict__ query, const float* __restrict__ ba,
            const float* __restrict__ bu) {
    int blk = blockIdx.x, tid = threadIdx.x;
    if (blk < HD) {
        int n = blk, k = tid;
        g_UaP[((size_t)(k >> 5) * HD + n) * 40 + (k & 31)] =
            __float2half_rn(Ua[(size_t)n * HD + k]);
    } else {
        int b = blk - HD;
        int o = tid;
        __shared__ float q[HD];
        q[o] = query[(size_t)b * HD + o];
        __syncthreads();
        const float4* wrow = (const float4*)(Wa + (size_t)o * HD);
        float a0 = 0.f, a1 = 0.f, a2 = 0.f, a3 = 0.f;
#pragma unroll 4
        for (int h = 0; h < HD / 4; h++) {
            float4 w = wrow[h];
            a0 += q[4 * h + 0] * w.x;
            a1 += q[4 * h + 1] * w.y;
            a2 += q[4 * h + 2] * w.z;
            a3 += q[4 * h + 3] * w.w;
        }
        g_c[(size_t)b * HD + o] = (a0 + a1) + (a2 + a3) + ba[o] + bu[o];
    }
}

// ---------------- GEMM pieces ----------------
__device__ __forceinline__ void loadA_regs(float4 (&v)[4], const float* __restrict__ keysB,
                                           int kc, int r, int kq) {
    const float* src = keysB + (size_t)r * HD + kc * KC + kq;
    v[0] = *(const float4*)(src);
    v[1] = *(const float4*)(src + 4);
    v[2] = *(const float4*)(src + 8);
    v[3] = *(const float4*)(src + 12);
}
// convert 16 floats -> fp16 into smem; optionally also STG to g_K16 (k16p != 0)
__device__ __forceinline__ void convert_storeA(const float4 (&v)[4], unsigned char* buf,
                                               int r, int kq, __half* k16p) {
    const float* f = (const float*)v;
    __half h[16];
#pragma unroll
    for (int i = 0; i < 16; i++) h[i] = __float2half_rn(f[i]);
    uint4* d = (uint4*)(buf + r * ROWB + kq * 2);
    d[0] = ((const uint4*)h)[0];
    d[1] = ((const uint4*)h)[1];
    if (k16p) {
        uint4* g = (uint4*)k16p;
        g[0] = ((const uint4*)h)[0];
        g[1] = ((const uint4*)h)[1];
    }
}
__device__ __forceinline__ void loadB(uint32_t dstB, const __half* __restrict__ src, int tid) {
    const unsigned char* s = (const unsigned char*)src;
#pragma unroll
    for (int i = tid; i < NT * 5; i += GT)
        cpasync16(dstB + i * 16, s + i * 16);
}

__global__ void __launch_bounds__(GT, 1)
gemm_scores_kernel(const float* __restrict__ keys, const float* __restrict__ Va) {
    extern __shared__ unsigned char smem[];
    uint32_t sb = smem_u32(smem);
    int tid = threadIdx.x, lid = tid & 31, wid = tid >> 5;
    int s0 = blockIdx.x * MT, b = blockIdx.y, nh = blockIdx.z;
    const float* keysB = keys + ((size_t)b * SSQ + s0) * HD;
    const __half* uaB = g_UaP + (size_t)nh * NT * 40;  // this n-half's B columns
    int wm = wid & 1, wn = wid >> 1;        // warp tile: rows wm*64(+64), cols wn*64(+64)
    int r = tid >> 1, kq = (tid & 1) * 16;  // A-conversion: 2 threads/row, 16 elems each

    // fp16-keys mirror base for this thread (nh==0 CTAs only)
    __half* k16base = (nh == 0)
        ? (g_K16 + ((size_t)b * SSQ + s0 + r) * HD + kq) : (__half*)0;

    {   // stage {c, Va} for this n-half
        float2* cv = (float2*)(smem + OF_CV);
        cv[tid] = make_float2(g_c[(size_t)b * HD + nh * NT + tid], Va[nh * NT + tid]);
    }

    // prologue
    float4 vr[4];
    loadA_regs(vr, keysB, 0, r, kq);
    loadB(sb + OF_Bb, uaB, tid);
    cpasync_commit();
    convert_storeA(vr, smem, r, kq, k16base);
    loadA_regs(vr, keysB, 1, r, kq);
    cpasync_waitall();
    __syncthreads();

    float acc[4][8][4];  // [row16 group][col8 group][frag]
#pragma unroll
    for (int i = 0; i < 4; i++)
#pragma unroll
        for (int j = 0; j < 8; j++)
#pragma unroll
            for (int c = 0; c < 4; c++) acc[i][j][c] = 0.f;

    uint32_t aoff = (lid & 15) * ROWB + (lid >> 4) * 16;

    for (int kc = 0; kc < NCH; kc++) {
        uint32_t curs = sb + (uint32_t)(kc & 1) * STGSZ;
        if (kc + 1 < NCH) {
            unsigned char* nxt = smem + ((kc + 1) & 1) * STGSZ;
            loadB(sb + (uint32_t)((kc + 1) & 1) * STGSZ + OF_Bb,
                  uaB + (size_t)(kc + 1) * HD * 40, tid);
            cpasync_commit();
            convert_storeA(vr, nxt, r, kq,
                           k16base ? k16base + (kc + 1) * KC : (__half*)0);
            if (kc + 2 < NCH) loadA_regs(vr, keysB, kc + 2, r, kq);
        }
#pragma unroll
        for (int ks = 0; ks < 2; ks++) {
            uint32_t kb = ks * 32;
            uint32_t ah[4][4], bb[4][4];
#pragma unroll
            for (int i = 0; i < 4; i++)
                ldsm4(ah[i], curs + (wm * 64 + i * 16) * ROWB + aoff + kb);
#pragma unroll
            for (int j2 = 0; j2 < 4; j2++)
                ldsm4(bb[j2], curs + OF_Bb + (wn * 64 + j2 * 16) * ROWB + aoff + kb);
#pragma unroll
            for (int i = 0; i < 4; i++)
#pragma unroll
                for (int j2 = 0; j2 < 4; j2++) {
                    mma16816(acc[i][2 * j2], ah[i], bb[j2][0], bb[j2][2]);
                    mma16816(acc[i][2 * j2 + 1], ah[i], bb[j2][1], bb[j2][3]);
                }
        }
        if (kc + 1 < NCH) {
            cpasync_waitall();
            __syncthreads();
        }
    }

    // epilogue: part[wn][row] = sum_{o in warp cols} Va[o]*tanh(D[row][o]+c[o])
    float* part = (float*)(smem + OF_PART);
    const float2* cv = (const float2*)(smem + OF_CV);
    __syncthreads();
#pragma unroll
    for (int i = 0; i < 4; i++) {
        float sA = 0.f, sB = 0.f;
#pragma unroll
        for (int j = 0; j < 8; j++) {
            int ol = wn * 64 + j * 8 + (lid & 3) * 2;
            float2 c0 = cv[ol], c1 = cv[ol + 1];
            sA += c0.y * tanhf(acc[i][j][0] + c0.x);
            sA += c1.y * tanhf(acc[i][j][1] + c1.x);
            sB += c0.y * tanhf(acc[i][j][2] + c0.x);
            sB += c1.y * tanhf(acc[i][j][3] + c1.x);
        }
        sA += __shfl_xor_sync(0xffffffffu, sA, 1);
        sA += __shfl_xor_sync(0xffffffffu, sA, 2);
        sB += __shfl_xor_sync(0xffffffffu, sB, 1);
        sB += __shfl_xor_sync(0xffffffffu, sB, 2);
        if ((lid & 3) == 0) {
            int row = wm * 64 + i * 16 + (lid >> 2);
            part[wn * 128 + row] = sA;
            part[wn * 128 + row + 8] = sB;
        }
    }
    __syncthreads();
    if (tid < MT) {
        float v = part[tid] + part[128 + tid] + part[256 + tid] + part[384 + tid];
        g_part[nh][(size_t)b * SSQ + s0 + tid] = v;
    }
}

// ---------------- softmax (sums the two n-half partial planes) ----------------
__global__ void softmax_kernel(float* __restrict__ wout) {
    int b = blockIdx.x, t = threadIdx.x;  // 256 threads
    __shared__ float sred[64];
    size_t base = (size_t)b * SSQ;
    float v[SSQ / 256];
    float m = -1e30f;
#pragma unroll
    for (int i = 0; i < SSQ / 256; i++) {
        v[i] = g_part[0][base + t + 256 * i] + g_part[1][base + t + 256 * i];
        m = fmaxf(m, v[i]);
    }
#pragma unroll
    for (int off = 16; off; off >>= 1) m = fmaxf(m, __shfl_xor_sync(0xffffffffu, m, off));
    if ((t & 31) == 0) sred[t >> 5] = m;
    __syncthreads();
    float M = sred[0];
#pragma unroll
    for (int j = 1; j < 8; j++) M = fmaxf(M, sred[j]);
    float sum = 0.f;
#pragma unroll
    for (int i = 0; i < SSQ / 256; i++) {
        float e = __expf(v[i] - M);
        v[i] = e;
        sum += e;
    }
#pragma unroll
    for (int off = 16; off; off >>= 1) sum += __shfl_xor_sync(0xffffffffu, sum, off);
    if ((t & 31) == 0) sred[32 + (t >> 5)] = sum;
    __syncthreads();
    float T = 0.f;
#pragma unroll
    for (int j = 0; j < 8; j++) T += sred[32 + j];
    float inv = 1.f / T;
#pragma unroll
    for (int i = 0; i < SSQ / 256; i++) {
        float wgt = v[i] * inv;
        g_scores[base + t + 256 * i] = wgt;
        if (wout) wout[base + t + 256 * i] = wgt;
    }
}

// ---------------- context from fp16 keys, split 4-way over s ----------------
__global__ void context_part_kernel() {
    int b = blockIdx.x, q = blockIdx.y;
    int h = threadIdx.x;  // 512
    __shared__ float w[SSQ / 4];
    w[h] = g_scores[(size_t)b * SSQ + q * (SSQ / 4) + h];
    __syncthreads();
    const __half* kb = g_K16 + ((size_t)b * SSQ + q * (SSQ / 4)) * HD + h;
    float acc = 0.f;
#pragma unroll 8
    for (int s = 0; s < SSQ / 4; s++) acc += w[s] * __half2float(kb[(size_t)s * HD]);
    g_cpart[q][(size_t)b * HD + h] = acc;
}
__global__ void context_combine_kernel(float* __restrict__ ctx) {
    int b = blockIdx.x, h = threadIdx.x;
    size_t i = (size_t)b * HD + h;
    ctx[i] = g_cpart[0][i] + g_cpart[1][i] + g_cpart[2][i] + g_cpart[3][i];
}

extern "C" void kernel_launch(void* const* d_in, const int* in_sizes, int n_in,
                              void* d_out, int out_size) {
    const float* query = (const float*)d_in[0];
    const float* keys  = (const float*)d_in[1];
    const float* Wa    = (const float*)d_in[2];
    const float* ba    = (const float*)d_in[3];
    const float* Ua    = (const float*)d_in[4];
    const float* bu    = (const float*)d_in[5];
    const float* Va    = (const float*)d_in[6];
    float* out = (float*)d_out;

    float* ctx_out = out;
    float* w_out = out + BB * HD;
    if (out_size == BB * SSQ) { ctx_out = nullptr; w_out = out; }
    else if (out_size == BB * HD) { w_out = nullptr; }

    static int smem_set = 0;
    if (!smem_set) {
        cudaFuncSetAttribute(gemm_scores_kernel,
                             cudaFuncAttributeMaxDynamicSharedMemorySize, SMEM_TOTAL);
        smem_set = 1;
    }

    prep_kernel<<<HD + BB, 512>>>(Ua, Wa, query, ba, bu);
    gemm_scores_kernel<<<dim3(SSQ / MT, BB, 2), GT, SMEM_TOTAL>>>(keys, Va);
    softmax_kernel<<<BB, 256>>>(w_out);
    context_part_kernel<<<dim3(BB, 4), 512>>>();
    if (ctx_out) context_combine_kernel<<<BB, HD>>>(ctx_out);
}

// round 12
// speedup vs baseline: 1.1846x; 1.1846x over previous
#include <cuda_runtime.h>
#include <cuda_fp16.h>
#include <cstdint>
#include <math.h>

#define HD 512
#define BB 128
#define SSQ 2048
#define MT 64         // s-rows per block
#define NT 512        // n-cols per block (full HD)
#define KC 32
#define NCH (HD / KC) // 16
#define ROWB 80       // padded smem row bytes (40 fp16, 64 valid) — conflict-free
#define GT 512        // gemm threads (16 warps, 2x8 grid of 32x64 tiles)
#define CSPLIT 8      // context s-split

// stage: A[64][80] @0 (5120), B[512][80] @5120 (40960) => 46080/stage, 2 stages
#define OF_Bb 5120
#define STGSZ 46080
#define OF_PART (2 * STGSZ)           // 92160, float[8][64] = 2KB
#define OF_CV (OF_PART + 2048)        // 94208, float2[512] = 4KB
#define SMEM_TOTAL (OF_CV + 4096)     // 98304

// ---------------- device scratch ----------------
__device__ float g_c[BB * HD];
__device__ float g_scores[BB * SSQ];
__device__ float g_cpart[CSPLIT][BB * HD];
__device__ __align__(16) __half g_K16[(size_t)BB * SSQ * HD];  // fp16 keys (written by GEMM)
__device__ __align__(16) __half g_UaP[(size_t)NCH * HD * 40];  // [kc][n][40] halves, 80B/row

// ---------------- helpers ----------------
__device__ __forceinline__ uint32_t smem_u32(const void* p) {
    uint32_t a;
    asm("{ .reg .u64 t; cvta.to.shared.u64 t, %1; cvt.u32.u64 %0, t; }" : "=r"(a) : "l"(p));
    return a;
}
__device__ __forceinline__ void cpasync16(uint32_t dst, const void* src) {
    asm volatile("cp.async.cg.shared.global [%0], [%1], 16;" :: "r"(dst), "l"(src));
}
__device__ __forceinline__ void cpasync_commit() {
    asm volatile("cp.async.commit_group;" ::: "memory");
}
__device__ __forceinline__ void cpasync_waitall() {
    asm volatile("cp.async.wait_group 0;" ::: "memory");
}
__device__ __forceinline__ void ldsm4(uint32_t (&r)[4], uint32_t addr) {
    asm volatile("ldmatrix.sync.aligned.m8n8.x4.shared.b16 {%0,%1,%2,%3}, [%4];"
                 : "=r"(r[0]), "=r"(r[1]), "=r"(r[2]), "=r"(r[3]) : "r"(addr));
}
__device__ __forceinline__ void mma16816(float (&d)[4], const uint32_t (&a)[4],
                                         uint32_t b0, uint32_t b1) {
    asm volatile(
        "mma.sync.aligned.m16n8k16.row.col.f32.f16.f16.f32 "
        "{%0,%1,%2,%3}, {%4,%5,%6,%7}, {%8,%9}, {%0,%1,%2,%3};"
        : "+f"(d[0]), "+f"(d[1]), "+f"(d[2]), "+f"(d[3])
        : "r"(a[0]), "r"(a[1]), "r"(a[2]), "r"(a[3]), "r"(b0), "r"(b1));
}

// ---------------- fused prep: Ua pack | c = q@Wa^T + ba + bu ----------------
__global__ void __launch_bounds__(512)
prep_kernel(const float* __restrict__ Ua, const float* __restrict__ Wa,
            const float* __restrict__ query, const float* __restrict__ ba,
            const float* __restrict__ bu) {
    int blk = blockIdx.x, tid = threadIdx.x;
    if (blk < HD) {
        int n = blk, k = tid;
        g_UaP[((size_t)(k >> 5) * HD + n) * 40 + (k & 31)] =
            __float2half_rn(Ua[(size_t)n * HD + k]);
    } else {
        int b = blk - HD;
        int o = tid;
        __shared__ float q[HD];
        q[o] = query[(size_t)b * HD + o];
        __syncthreads();
        const float4* wrow = (const float4*)(Wa + (size_t)o * HD);
        float a0 = 0.f, a1 = 0.f, a2 = 0.f, a3 = 0.f;
#pragma unroll 4
        for (int h = 0; h < HD / 4; h++) {
            float4 w = wrow[h];
            a0 += q[4 * h + 0] * w.x;
            a1 += q[4 * h + 1] * w.y;
            a2 += q[4 * h + 2] * w.z;
            a3 += q[4 * h + 3] * w.w;
        }
        g_c[(size_t)b * HD + o] = (a0 + a1) + (a2 + a3) + ba[o] + bu[o];
    }
}

// ---------------- GEMM pieces ----------------
// A conversion: 512 threads cover 64 rows x 32 cols; 4 floats each.
__device__ __forceinline__ void convertA(const float4 v, unsigned char* buf,
                                         int r, int kq, __half* k16p) {
    __half h[4];
    h[0] = __float2half_rn(v.x);
    h[1] = __float2half_rn(v.y);
    h[2] = __float2half_rn(v.z);
    h[3] = __float2half_rn(v.w);
    *(uint2*)(buf + r * ROWB + kq * 2) = *(const uint2*)h;
    *(uint2*)k16p = *(const uint2*)h;
}
__device__ __forceinline__ void loadB(uint32_t dstB, const __half* __restrict__ src, int tid) {
    const unsigned char* s = (const unsigned char*)src;
#pragma unroll
    for (int i = tid; i < NT * 5; i += GT)
        cpasync16(dstB + i * 16, s + i * 16);
}

__global__ void __launch_bounds__(GT, 1)
gemm_scores_kernel(const float* __restrict__ keys, const float* __restrict__ Va) {
    extern __shared__ unsigned char smem[];
    uint32_t sb = smem_u32(smem);
    int tid = threadIdx.x, lid = tid & 31, wid = tid >> 5;
    int s0 = blockIdx.x * MT, b = blockIdx.y;
    const float* keysB = keys + ((size_t)b * SSQ + s0) * HD;
    int wm = wid & 1, wn = wid >> 1;        // warp tile: rows wm*32(+32), cols wn*64(+64)
    int r = tid >> 3, kq = (tid & 7) * 4;   // A-conversion: 8 threads/row, 4 elems each
    __half* k16base = g_K16 + ((size_t)b * SSQ + s0 + r) * HD + kq;

    {   // stage {c, Va}
        float2* cv = (float2*)(smem + OF_CV);
        cv[tid] = make_float2(g_c[(size_t)b * HD + tid], Va[tid]);
    }

    // prologue
    float4 vr = *(const float4*)(keysB + (size_t)r * HD + kq);
    loadB(sb + OF_Bb, g_UaP, tid);
    cpasync_commit();
    convertA(vr, smem, r, kq, k16base);
    vr = *(const float4*)(keysB + (size_t)r * HD + KC + kq);
    cpasync_waitall();
    __syncthreads();

    float acc[2][8][4];  // [row16 group][col8 group][frag]
#pragma unroll
    for (int i = 0; i < 2; i++)
#pragma unroll
        for (int j = 0; j < 8; j++)
#pragma unroll
            for (int c = 0; c < 4; c++) acc[i][j][c] = 0.f;

    uint32_t aoff = (lid & 15) * ROWB + (lid >> 4) * 16;

    for (int kc = 0; kc < NCH; kc++) {
        uint32_t curs = sb + (uint32_t)(kc & 1) * STGSZ;
        if (kc + 1 < NCH) {
            unsigned char* nxt = smem + ((kc + 1) & 1) * STGSZ;
            loadB(sb + (uint32_t)((kc + 1) & 1) * STGSZ + OF_Bb,
                  g_UaP + (size_t)(kc + 1) * HD * 40, tid);
            cpasync_commit();
            convertA(vr, nxt, r, kq, k16base + (kc + 1) * KC);
            if (kc + 2 < NCH)
                vr = *(const float4*)(keysB + (size_t)r * HD + (kc + 2) * KC + kq);
        }
#pragma unroll
        for (int ks = 0; ks < 2; ks++) {
            uint32_t kb = ks * 32;
            uint32_t ah[2][4], bb[4][4];
#pragma unroll
            for (int i = 0; i < 2; i++)
                ldsm4(ah[i], curs + (wm * 32 + i * 16) * ROWB + aoff + kb);
#pragma unroll
            for (int j2 = 0; j2 < 4; j2++)
                ldsm4(bb[j2], curs + OF_Bb + (wn * 64 + j2 * 16) * ROWB + aoff + kb);
#pragma unroll
            for (int i = 0; i < 2; i++)
#pragma unroll
                for (int j2 = 0; j2 < 4; j2++) {
                    mma16816(acc[i][2 * j2], ah[i], bb[j2][0], bb[j2][2]);
                    mma16816(acc[i][2 * j2 + 1], ah[i], bb[j2][1], bb[j2][3]);
                }
        }
        if (kc + 1 < NCH) {
            cpasync_waitall();
            __syncthreads();
        }
    }

    // epilogue: part[wn][row] = sum_{o in warp cols} Va[o]*tanh(D[row][o]+c[o])
    float* part = (float*)(smem + OF_PART);
    const float2* cv = (const float2*)(smem + OF_CV);
    __syncthreads();
#pragma unroll
    for (int i = 0; i < 2; i++) {
        float sA = 0.f, sB = 0.f;
#pragma unroll
        for (int j = 0; j < 8; j++) {
            int ol = wn * 64 + j * 8 + (lid & 3) * 2;
            float2 c0 = cv[ol], c1 = cv[ol + 1];
            sA += c0.y * tanhf(acc[i][j][0] + c0.x);
            sA += c1.y * tanhf(acc[i][j][1] + c1.x);
            sB += c0.y * tanhf(acc[i][j][2] + c0.x);
            sB += c1.y * tanhf(acc[i][j][3] + c1.x);
        }
        sA += __shfl_xor_sync(0xffffffffu, sA, 1);
        sA += __shfl_xor_sync(0xffffffffu, sA, 2);
        sB += __shfl_xor_sync(0xffffffffu, sB, 1);
        sB += __shfl_xor_sync(0xffffffffu, sB, 2);
        if ((lid & 3) == 0) {
            int row = wm * 32 + i * 16 + (lid >> 2);
            part[wn * 64 + row] = sA;
            part[wn * 64 + row + 8] = sB;
        }
    }
    __syncthreads();
    if (tid < MT) {
        float v = 0.f;
#pragma unroll
        for (int p = 0; p < 8; p++) v += part[p * 64 + tid];
        g_scores[(size_t)b * SSQ + s0 + tid] = v;
    }
}

// ---------------- softmax over S per batch ----------------
__global__ void softmax_kernel(float* __restrict__ wout) {
    int b = blockIdx.x, t = threadIdx.x;  // 256 threads
    __shared__ float sred[64];
    size_t base = (size_t)b * SSQ;
    float v[SSQ / 256];
    float m = -1e30f;
#pragma unroll
    for (int i = 0; i < SSQ / 256; i++) {
        v[i] = g_scores[base + t + 256 * i];
        m = fmaxf(m, v[i]);
    }
#pragma unroll
    for (int off = 16; off; off >>= 1) m = fmaxf(m, __shfl_xor_sync(0xffffffffu, m, off));
    if ((t & 31) == 0) sred[t >> 5] = m;
    __syncthreads();
    float M = sred[0];
#pragma unroll
    for (int j = 1; j < 8; j++) M = fmaxf(M, sred[j]);
    float sum = 0.f;
#pragma unroll
    for (int i = 0; i < SSQ / 256; i++) {
        float e = __expf(v[i] - M);
        v[i] = e;
        sum += e;
    }
#pragma unroll
    for (int off = 16; off; off >>= 1) sum += __shfl_xor_sync(0xffffffffu, sum, off);
    if ((t & 31) == 0) sred[32 + (t >> 5)] = sum;
    __syncthreads();
    float T = 0.f;
#pragma unroll
    for (int j = 0; j < 8; j++) T += sred[32 + j];
    float inv = 1.f / T;
#pragma unroll
    for (int i = 0; i < SSQ / 256; i++) {
        float wgt = v[i] * inv;
        g_scores[base + t + 256 * i] = wgt;
        if (wout) wout[base + t + 256 * i] = wgt;
    }
}

// ---------------- context from fp16 keys, split 8-way over s ----------------
__global__ void context_part_kernel() {
    int b = blockIdx.x, q = blockIdx.y;
    int t = threadIdx.x;  // 256, each owns a half2 column pair
    __shared__ float w[SSQ / CSPLIT];
    if (t < SSQ / CSPLIT) w[t] = g_scores[(size_t)b * SSQ + q * (SSQ / CSPLIT) + t];
    __syncthreads();
    const __half2* kb =
        (const __half2*)(g_K16 + ((size_t)b * SSQ + q * (SSQ / CSPLIT)) * HD) + t;
    float ax = 0.f, ay = 0.f;
#pragma unroll 8
    for (int s = 0; s < SSQ / CSPLIT; s++) {
        float2 f = __half22float2(kb[(size_t)s * (HD / 2)]);
        float ws = w[s];
        ax += ws * f.x;
        ay += ws * f.y;
    }
    g_cpart[q][(size_t)b * HD + 2 * t] = ax;
    g_cpart[q][(size_t)b * HD + 2 * t + 1] = ay;
}
__global__ void context_combine_kernel(float* __restrict__ ctx) {
    int b = blockIdx.x, h = threadIdx.x;
    size_t i = (size_t)b * HD + h;
    float v = 0.f;
#pragma unroll
    for (int q = 0; q < CSPLIT; q++) v += g_cpart[q][i];
    ctx[i] = v;
}

extern "C" void kernel_launch(void* const* d_in, const int* in_sizes, int n_in,
                              void* d_out, int out_size) {
    const float* query = (const float*)d_in[0];
    const float* keys  = (const float*)d_in[1];
    const float* Wa    = (const float*)d_in[2];
    const float* ba    = (const float*)d_in[3];
    const float* Ua    = (const float*)d_in[4];
    const float* bu    = (const float*)d_in[5];
    const float* Va    = (const float*)d_in[6];
    float* out = (float*)d_out;

    float* ctx_out = out;
    float* w_out = out + BB * HD;
    if (out_size == BB * SSQ) { ctx_out = nullptr; w_out = out; }
    else if (out_size == BB * HD) { w_out = nullptr; }

    static int smem_set = 0;
    if (!smem_set) {
        cudaFuncSetAttribute(gemm_scores_kernel,
                             cudaFuncAttributeMaxDynamicSharedMemorySize, SMEM_TOTAL);
        smem_set = 1;
    }

    prep_kernel<<<HD + BB, 512>>>(Ua, Wa, query, ba, bu);
    gemm_scores_kernel<<<dim3(SSQ / MT, BB), GT, SMEM_TOTAL>>>(keys, Va);
    softmax_kernel<<<BB, 256>>>(w_out);
    context_part_kernel<<<dim3(BB, CSPLIT), 256>>>();
    if (ctx_out) context_combine_kernel<<<BB, HD>>>(ctx_out);
}

// round 15
// speedup vs baseline: 1.1992x; 1.0123x over previous
#include <cuda_runtime.h>
#include <cuda_fp16.h>
#include <cstdint>
#include <math.h>

#define HD 512
#define BB 128
#define SSQ 2048
#define MT 64         // s-rows per block
#define NT 256        // n-cols per block (half of HD)
#define KC 32
#define NCH (HD / KC) // 16
#define ROWB 80       // padded smem row bytes (40 fp16, 64 valid) — conflict-free
#define GT 256        // gemm threads (8 warps, 2x4 grid of 32x64 tiles)
#define CSPLIT 8      // context s-split

// stage: A[64][80] @0 (5120), B[256][80] @5120 (20480) => 25600/stage, 2 stages
#define OF_Bb 5120
#define STGSZ 25600
#define OF_PART (2 * STGSZ)           // 51200, float[4][64] = 1KB
#define OF_CV (OF_PART + 1024)        // 52224, float2[256] = 2KB
#define SMEM_TOTAL (OF_CV + 2048)     // 54272  -> 2 CTAs/SM

// ---------------- device scratch ----------------
__device__ float g_c[BB * HD];
__device__ float g_scores[BB * SSQ];
__device__ float g_part[2][BB * SSQ];
__device__ float g_cpart[CSPLIT][BB * HD];
__device__ __align__(16) __half g_K16[(size_t)BB * SSQ * HD];  // fp16 keys (nh=0 CTAs)
__device__ __align__(16) __half g_UaP[(size_t)NCH * HD * 40];  // [kc][n][40] halves

// ---------------- helpers ----------------
__device__ __forceinline__ uint32_t smem_u32(const void* p) {
    uint32_t a;
    asm("{ .reg .u64 t; cvta.to.shared.u64 t, %1; cvt.u32.u64 %0, t; }" : "=r"(a) : "l"(p));
    return a;
}
__device__ __forceinline__ void cpasync16(uint32_t dst, const void* src) {
    asm volatile("cp.async.cg.shared.global [%0], [%1], 16;" :: "r"(dst), "l"(src));
}
__device__ __forceinline__ void cpasync_commit() {
    asm volatile("cp.async.commit_group;" ::: "memory");
}
__device__ __forceinline__ void cpasync_waitall() {
    asm volatile("cp.async.wait_group 0;" ::: "memory");
}
__device__ __forceinline__ void ldsm4(uint32_t (&r)[4], uint32_t addr) {
    asm volatile("ldmatrix.sync.aligned.m8n8.x4.shared.b16 {%0,%1,%2,%3}, [%4];"
                 : "=r"(r[0]), "=r"(r[1]), "=r"(r[2]), "=r"(r[3]) : "r"(addr));
}
__device__ __forceinline__ void mma16816(float (&d)[4], const uint32_t (&a)[4],
                                         uint32_t b0, uint32_t b1) {
    asm volatile(
        "mma.sync.aligned.m16n8k16.row.col.f32.f16.f16.f32 "
        "{%0,%1,%2,%3}, {%4,%5,%6,%7}, {%8,%9}, {%0,%1,%2,%3};"
        : "+f"(d[0]), "+f"(d[1]), "+f"(d[2]), "+f"(d[3])
        : "r"(a[0]), "r"(a[1]), "r"(a[2]), "r"(a[3]), "r"(b0), "r"(b1));
}

// ---------------- fused prep: Ua pack | c = q@Wa^T + ba + bu ----------------
__global__ void __launch_bounds__(512)
prep_kernel(const float* __restrict__ Ua, const float* __restrict__ Wa,
            const float* __restrict__ query, const float* __restrict__ ba,
            const float* __restrict__ bu) {
    int blk = blockIdx.x, tid = threadIdx.x;
    if (blk < HD) {
        int n = blk, k = tid;
        g_UaP[((size_t)(k >> 5) * HD + n) * 40 + (k & 31)] =
            __float2half_rn(Ua[(size_t)n * HD + k]);
    } else {
        int b = blk - HD;
        int o = tid;
        __shared__ float q[HD];
        q[o] = query[(size_t)b * HD + o];
        __syncthreads();
        const float4* wrow = (const float4*)(Wa + (size_t)o * HD);
        float a0 = 0.f, a1 = 0.f, a2 = 0.f, a3 = 0.f;
#pragma unroll 4
        for (int h = 0; h < HD / 4; h++) {
            float4 w = wrow[h];
            a0 += q[4 * h + 0] * w.x;
            a1 += q[4 * h + 1] * w.y;
            a2 += q[4 * h + 2] * w.z;
            a3 += q[4 * h + 3] * w.w;
        }
        g_c[(size_t)b * HD + o] = (a0 + a1) + (a2 + a3) + ba[o] + bu[o];
    }
}

// ---------------- GEMM pieces ----------------
// A conversion: 256 threads cover 64 rows x 32 cols; 8 floats each (4/row-chunk x2).
__device__ __forceinline__ void loadA_regs(float4 (&v)[2], const float* __restrict__ keysB,
                                           int kc, int r, int kq) {
    const float* src = keysB + (size_t)r * HD + kc * KC + kq;
    v[0] = *(const float4*)(src);
    v[1] = *(const float4*)(src + 4);
}
__device__ __forceinline__ void convertA(const float4 (&v)[2], unsigned char* buf,
                                         int r, int kq, __half* k16p) {
    const float* f = (const float*)v;
    __half h[8];
#pragma unroll
    for (int i = 0; i < 8; i++) h[i] = __float2half_rn(f[i]);
    *(uint4*)(buf + r * ROWB + kq * 2) = *(const uint4*)h;
    if (k16p) *(uint4*)k16p = *(const uint4*)h;
}
__device__ __forceinline__ void loadB(uint32_t dstB, const __half* __restrict__ src, int tid) {
    const unsigned char* s = (const unsigned char*)src;
#pragma unroll
    for (int i = tid; i < NT * 5; i += GT)
        cpasync16(dstB + i * 16, s + i * 16);
}

__global__ void __launch_bounds__(GT, 2)
gemm_scores_kernel(const float* __restrict__ keys, const float* __restrict__ Va) {
    extern __shared__ unsigned char smem[];
    uint32_t sb = smem_u32(smem);
    int tid = threadIdx.x, lid = tid & 31, wid = tid >> 5;
    int s0 = blockIdx.x * MT, b = blockIdx.y, nh = blockIdx.z;
    const float* keysB = keys + ((size_t)b * SSQ + s0) * HD;
    const __half* uaB = g_UaP + (size_t)nh * NT * 40;  // this n-half's B columns
    int wm = wid & 1, wn = wid >> 1;        // warp tile: rows wm*32(+32), cols wn*64(+64)
    int r = tid >> 2, kq = (tid & 3) * 8;   // A-conversion: 4 threads/row, 8 elems each
    __half* k16base = (nh == 0)
        ? (g_K16 + ((size_t)b * SSQ + s0 + r) * HD + kq) : (__half*)0;

    {   // stage {c, Va} for this n-half
        float2* cv = (float2*)(smem + OF_CV);
        cv[tid] = make_float2(g_c[(size_t)b * HD + nh * NT + tid], Va[nh * NT + tid]);
    }

    // prologue
    float4 vr[2];
    loadA_regs(vr, keysB, 0, r, kq);
    loadB(sb + OF_Bb, uaB, tid);
    cpasync_commit();
    convertA(vr, smem, r, kq, k16base);
    loadA_regs(vr, keysB, 1, r, kq);
    cpasync_waitall();
    __syncthreads();

    float acc[2][8][4];  // [row16 group][col8 group][frag]
#pragma unroll
    for (int i = 0; i < 2; i++)
#pragma unroll
        for (int j = 0; j < 8; j++)
#pragma unroll
            for (int c = 0; c < 4; c++) acc[i][j][c] = 0.f;

    uint32_t aoff = (lid & 15) * ROWB + (lid >> 4) * 16;

    for (int kc = 0; kc < NCH; kc++) {
        uint32_t curs = sb + (uint32_t)(kc & 1) * STGSZ;
        if (kc + 1 < NCH) {
            unsigned char* nxt = smem + ((kc + 1) & 1) * STGSZ;
            loadB(sb + (uint32_t)((kc + 1) & 1) * STGSZ + OF_Bb,
                  uaB + (size_t)(kc + 1) * HD * 40, tid);
            cpasync_commit();
            convertA(vr, nxt, r, kq, k16base ? k16base + (kc + 1) * KC : (__half*)0);
            if (kc + 2 < NCH) loadA_regs(vr, keysB, kc + 2, r, kq);
        }
#pragma unroll
        for (int ks = 0; ks < 2; ks++) {
            uint32_t kb = ks * 32;
            uint32_t ah[2][4], bb[4][4];
#pragma unroll
            for (int i = 0; i < 2; i++)
                ldsm4(ah[i], curs + (wm * 32 + i * 16) * ROWB + aoff + kb);
#pragma unroll
            for (int j2 = 0; j2 < 4; j2++)
                ldsm4(bb[j2], curs + OF_Bb + (wn * 64 + j2 * 16) * ROWB + aoff + kb);
#pragma unroll
            for (int i = 0; i < 2; i++)
#pragma unroll
                for (int j2 = 0; j2 < 4; j2++) {
                    mma16816(acc[i][2 * j2], ah[i], bb[j2][0], bb[j2][2]);
                    mma16816(acc[i][2 * j2 + 1], ah[i], bb[j2][1], bb[j2][3]);
                }
        }
        if (kc + 1 < NCH) {
            cpasync_waitall();
            __syncthreads();
        }
    }

    // epilogue: part[wn][row] = sum_{o in warp cols} Va[o]*tanh(D[row][o]+c[o])
    float* part = (float*)(smem + OF_PART);
    const float2* cv = (const float2*)(smem + OF_CV);
    __syncthreads();
#pragma unroll
    for (int i = 0; i < 2; i++) {
        float sA = 0.f, sB = 0.f;
#pragma unroll
        for (int j = 0; j < 8; j++) {
            int ol = wn * 64 + j * 8 + (lid & 3) * 2;
            float2 c0 = cv[ol], c1 = cv[ol + 1];
            sA += c0.y * tanhf(acc[i][j][0] + c0.x);
            sA += c1.y * tanhf(acc[i][j][1] + c1.x);
            sB += c0.y * tanhf(acc[i][j][2] + c0.x);
            sB += c1.y * tanhf(acc[i][j][3] + c1.x);
        }
        sA += __shfl_xor_sync(0xffffffffu, sA, 1);
        sA += __shfl_xor_sync(0xffffffffu, sA, 2);
        sB += __shfl_xor_sync(0xffffffffu, sB, 1);
        sB += __shfl_xor_sync(0xffffffffu, sB, 2);
        if ((lid & 3) == 0) {
            int row = wm * 32 + i * 16 + (lid >> 2);
            part[wn * 64 + row] = sA;
            part[wn * 64 + row + 8] = sB;
        }
    }
    __syncthreads();
    if (tid < MT) {
        float v = part[tid] + part[64 + tid] + part[128 + tid] + part[192 + tid];
        g_part[nh][(size_t)b * SSQ + s0 + tid] = v;
    }
}

// ---------------- softmax (sums the two n-half partial planes) ----------------
__global__ void softmax_kernel(float* __restrict__ wout) {
    int b = blockIdx.x, t = threadIdx.x;  // 256 threads
    __shared__ float sred[64];
    size_t base = (size_t)b * SSQ;
    float v[SSQ / 256];
    float m = -1e30f;
#pragma unroll
    for (int i = 0; i < SSQ / 256; i++) {
        v[i] = g_part[0][base + t + 256 * i] + g_part[1][base + t + 256 * i];
        m = fmaxf(m, v[i]);
    }
#pragma unroll
    for (int off = 16; off; off >>= 1) m = fmaxf(m, __shfl_xor_sync(0xffffffffu, m, off));
    if ((t & 31) == 0) sred[t >> 5] = m;
    __syncthreads();
    float M = sred[0];
#pragma unroll
    for (int j = 1; j < 8; j++) M = fmaxf(M, sred[j]);
    float sum = 0.f;
#pragma unroll
    for (int i = 0; i < SSQ / 256; i++) {
        float e = __expf(v[i] - M);
        v[i] = e;
        sum += e;
    }
#pragma unroll
    for (int off = 16; off; off >>= 1) sum += __shfl_xor_sync(0xffffffffu, sum, off);
    if ((t & 31) == 0) sred[32 + (t >> 5)] = sum;
    __syncthreads();
    float T = 0.f;
#pragma unroll
    for (int j = 0; j < 8; j++) T += sred[32 + j];
    float inv = 1.f / T;
#pragma unroll
    for (int i = 0; i < SSQ / 256; i++) {
        float wgt = v[i] * inv;
        g_scores[base + t + 256 * i] = wgt;
        if (wout) wout[base + t + 256 * i] = wgt;
    }
}

// ---------------- context from fp16 keys, split 8-way over s ----------------
__global__ void context_part_kernel() {
    int b = blockIdx.x, q = blockIdx.y;
    int t = threadIdx.x;  // 256, each owns a half2 column pair
    __shared__ float w[SSQ / CSPLIT];
    if (t < SSQ / CSPLIT) w[t] = g_scores[(size_t)b * SSQ + q * (SSQ / CSPLIT) + t];
    __syncthreads();
    const __half2* kb =
        (const __half2*)(g_K16 + ((size_t)b * SSQ + q * (SSQ / CSPLIT)) * HD) + t;
    float ax = 0.f, ay = 0.f;
#pragma unroll 8
    for (int s = 0; s < SSQ / CSPLIT; s++) {
        float2 f = __half22float2(kb[(size_t)s * (HD / 2)]);
        float ws = w[s];
        ax += ws * f.x;
        ay += ws * f.y;
    }
    g_cpart[q][(size_t)b * HD + 2 * t] = ax;
    g_cpart[q][(size_t)b * HD + 2 * t + 1] = ay;
}
__global__ void context_combine_kernel(float* __restrict__ ctx) {
    int b = blockIdx.x, h = threadIdx.x;
    size_t i = (size_t)b * HD + h;
    float v = 0.f;
#pragma unroll
    for (int q = 0; q < CSPLIT; q++) v += g_cpart[q][i];
    ctx[i] = v;
}

extern "C" void kernel_launch(void* const* d_in, const int* in_sizes, int n_in,
                              void* d_out, int out_size) {
    const float* query = (const float*)d_in[0];
    const float* keys  = (const float*)d_in[1];
    const float* Wa    = (const float*)d_in[2];
    const float* ba    = (const float*)d_in[3];
    const float* Ua    = (const float*)d_in[4];
    const float* bu    = (const float*)d_in[5];
    const float* Va    = (const float*)d_in[6];
    float* out = (float*)d_out;

    float* ctx_out = out;
    float* w_out = out + BB * HD;
    if (out_size == BB * SSQ) { ctx_out = nullptr; w_out = out; }
    else if (out_size == BB * HD) { w_out = nullptr; }

    static int smem_set = 0;
    if (!smem_set) {
        cudaFuncSetAttribute(gemm_scores_kernel,
                             cudaFuncAttributeMaxDynamicSharedMemorySize, SMEM_TOTAL);
        smem_set = 1;
    }

    prep_kernel<<<HD + BB, 512>>>(Ua, Wa, query, ba, bu);
    gemm_scores_kernel<<<dim3(SSQ / MT, BB, 2), GT, SMEM_TOTAL>>>(keys, Va);
    softmax_kernel<<<BB, 256>>>(w_out);
    context_part_kernel<<<dim3(BB, CSPLIT), 256>>>();
    if (ctx_out) context_combine_kernel<<<BB, HD>>>(ctx_out);
}